// round 2
// baseline (speedup 1.0000x reference)
#include <cuda_runtime.h>

// Problem constants
#define NB   8
#define NT   4096
#define ND   512
#define NDI  1024
#define NM   (NB * NT)   // 32768 rows (B*T)

// ---------------------------------------------------------------------------
// Scratch (static __device__ arrays; no allocations allowed)
// ---------------------------------------------------------------------------
__device__ float g_Xp[NM * NDI];   // x_proj            (128 MB)
__device__ float g_Z [NM * NDI];   // z                 (128 MB)
__device__ float g_Af[NM * NDI];   // conv-fwd output   (A matrix for fwd proj GEMM)
__device__ float g_Ab[NM * NDI];   // conv-bwd output   (A matrix for bwd proj GEMM)
__device__ float g_Gf[NM * NDI];   // fwd proj GEMM out (pre-bias, pre-silu)
__device__ float g_Gb[NM * NDI];   // bwd proj GEMM out
__device__ float g_Y [NM * NDI];   // gated mixer output
__device__ float g_H [NM * ND ];   // residual + out_proj (pre-LN)

__device__ __forceinline__ float silu_f(float x) {
    return x / (1.0f + __expf(-x));
}

// ---------------------------------------------------------------------------
// Generic SGEMM: C[m,n] = sum_k A[m,k] * W[n,k]
//   A: M x K row-major (K contiguous), W: N x K row-major (K contiguous)
//   BM=BN=128, BK=8, 256 threads, 8x8 per-thread tiles, float4 everywhere.
//   mode 0: split store: n <  NDI -> C0[m*NDI+n]   (x_proj)
//                        n >= NDI -> C1[m*NDI+n-NDI] (z)
//   mode 1: C0[m*N+n] = acc
//   mode 2: C0[m*N+n] = acc + R[m*N+n]   (residual add)
// ---------------------------------------------------------------------------
__global__ __launch_bounds__(256, 2)
void sgemm128(const float* __restrict__ A, const float* __restrict__ W,
              float* __restrict__ C0, float* __restrict__ C1,
              const float* __restrict__ R, int K, int N, int mode)
{
    __shared__ float As[8][128];
    __shared__ float Ws[8][128];

    const int tid  = threadIdx.x;
    const int lrow = tid >> 1;          // 0..127
    const int lk   = (tid & 1) << 2;    // 0 or 4
    const int m0   = blockIdx.y << 7;
    const int n0   = blockIdx.x << 7;

    const float* Ap = A + (m0 + lrow) * K + lk;
    const float* Wp = W + (n0 + lrow) * K + lk;

    const int tx = tid & 15;
    const int ty = tid >> 4;

    float acc[8][8];
#pragma unroll
    for (int i = 0; i < 8; ++i)
#pragma unroll
        for (int j = 0; j < 8; ++j) acc[i][j] = 0.0f;

    float4 av = *(const float4*)(Ap);
    float4 wv = *(const float4*)(Wp);

    for (int k0 = 0; k0 < K; k0 += 8) {
        As[lk + 0][lrow] = av.x; As[lk + 1][lrow] = av.y;
        As[lk + 2][lrow] = av.z; As[lk + 3][lrow] = av.w;
        Ws[lk + 0][lrow] = wv.x; Ws[lk + 1][lrow] = wv.y;
        Ws[lk + 2][lrow] = wv.z; Ws[lk + 3][lrow] = wv.w;
        __syncthreads();

        if (k0 + 8 < K) {                    // prefetch next K-slab
            av = *(const float4*)(Ap + k0 + 8);
            wv = *(const float4*)(Wp + k0 + 8);
        }

#pragma unroll
        for (int k = 0; k < 8; ++k) {
            float a[8], b[8];
            *(float4*)&a[0] = *(const float4*)&As[k][ty * 8];
            *(float4*)&a[4] = *(const float4*)&As[k][ty * 8 + 4];
            *(float4*)&b[0] = *(const float4*)&Ws[k][tx * 8];
            *(float4*)&b[4] = *(const float4*)&Ws[k][tx * 8 + 4];
#pragma unroll
            for (int i = 0; i < 8; ++i)
#pragma unroll
                for (int j = 0; j < 8; ++j)
                    acc[i][j] = fmaf(a[i], b[j], acc[i][j]);
        }
        __syncthreads();
    }

    // Epilogue
#pragma unroll
    for (int i = 0; i < 8; ++i) {
        const int m = m0 + ty * 8 + i;
#pragma unroll
        for (int jj = 0; jj < 2; ++jj) {
            const int n = n0 + tx * 8 + jj * 4;
            float4 v = make_float4(acc[i][jj*4+0], acc[i][jj*4+1],
                                   acc[i][jj*4+2], acc[i][jj*4+3]);
            if (mode == 0) {
                if (n < NDI) *(float4*)(C0 + m * NDI + n)       = v;
                else         *(float4*)(C1 + m * NDI + (n-NDI)) = v;
            } else if (mode == 1) {
                *(float4*)(C0 + m * N + n) = v;
            } else {
                const float4 r = *(const float4*)(R + m * N + n);
                v.x += r.x; v.y += r.y; v.z += r.z; v.w += r.w;
                *(float4*)(C0 + m * N + n) = v;
            }
        }
    }
}

// ---------------------------------------------------------------------------
// Depthwise causal (fwd) + anti-causal (bwd) conv, per batch.
//   Af[t,c] = bf[c] + sum_{k=0..6} wf[c,k] * xp[t-7+k, c]   (t within batch)
//   Ab[t,c] = bb[c] + sum_{k=0..6} wb[c,k] * xp[t+7-k, c]
// Out-of-batch rows are zero (padding). Shift-right is folded into the
// index offsets; the t==0 / t==T-1 full-row masks are applied in combine.
// ---------------------------------------------------------------------------
__global__ void conv_kernel(const float* __restrict__ wf, const float* __restrict__ bf,
                            const float* __restrict__ wb, const float* __restrict__ bb)
{
    const int c = blockIdx.x * blockDim.x + threadIdx.x;   // 0..NDI-1
    const int m = blockIdx.y;                              // 0..NM-1
    const int t = m & (NT - 1);

    float accf = bf[c];
    float accb = bb[c];
#pragma unroll
    for (int k = 0; k < 7; ++k) {
        const int tf = t - 7 + k;
        if (tf >= 0)
            accf = fmaf(wf[c * 7 + k], g_Xp[(m - 7 + k) * NDI + c], accf);
        const int tb = t + 7 - k;
        if (tb < NT)
            accb = fmaf(wb[c * 7 + k], g_Xp[(m + 7 - k) * NDI + c], accb);
    }
    g_Af[m * NDI + c] = accf;
    g_Ab[m * NDI + c] = accb;
}

// ---------------------------------------------------------------------------
// Combine: y = mask_f*silu(Gf+pbf) + mask_b*silu(Gb+pbb) + Xp*diag
//          y *= silu(z) * gate_scale
// ---------------------------------------------------------------------------
__global__ void combine_kernel(const float* __restrict__ pbf, const float* __restrict__ pbb,
                               const float* __restrict__ diag, const float* __restrict__ gsp)
{
    const int i4   = blockIdx.x * blockDim.x + threadIdx.x;
    const int base = i4 * 4;                 // element index into NM*NDI
    const int c    = base & (NDI - 1);
    const int m    = base >> 10;             // NDI == 1024
    const int t    = m & (NT - 1);

    const float fm = (t > 0)      ? 1.0f : 0.0f;
    const float bm = (t < NT - 1) ? 1.0f : 0.0f;
    const float gs = gsp[0];

    const float4 gf = *(const float4*)(g_Gf + base);
    const float4 gb = *(const float4*)(g_Gb + base);
    const float4 xp = *(const float4*)(g_Xp + base);
    const float4 zz = *(const float4*)(g_Z  + base);
    const float4 pf = *(const float4*)(pbf + c);
    const float4 pb = *(const float4*)(pbb + c);
    const float4 dg = *(const float4*)(diag + c);

    float4 y;
    y.x = fm * silu_f(gf.x + pf.x) + bm * silu_f(gb.x + pb.x) + xp.x * dg.x;
    y.y = fm * silu_f(gf.y + pf.y) + bm * silu_f(gb.y + pb.y) + xp.y * dg.y;
    y.z = fm * silu_f(gf.z + pf.z) + bm * silu_f(gb.z + pb.z) + xp.z * dg.z;
    y.w = fm * silu_f(gf.w + pf.w) + bm * silu_f(gb.w + pb.w) + xp.w * dg.w;

    y.x *= silu_f(zz.x) * gs;
    y.y *= silu_f(zz.y) * gs;
    y.z *= silu_f(zz.z) * gs;
    y.w *= silu_f(zz.w) * gs;

    *(float4*)(g_Y + base) = y;
}

// ---------------------------------------------------------------------------
// LayerNorm over last dim (512), one block (128 threads) per row.
// ---------------------------------------------------------------------------
__global__ void ln_kernel(const float* __restrict__ lng, const float* __restrict__ lnb,
                          float* __restrict__ out)
{
    const int row = blockIdx.x;
    const int tid = threadIdx.x;                 // 0..127

    const float4 v = ((const float4*)(g_H + (size_t)row * ND))[tid];
    float s  = v.x + v.y + v.z + v.w;
    float ss = v.x*v.x + v.y*v.y + v.z*v.z + v.w*v.w;

#pragma unroll
    for (int o = 16; o > 0; o >>= 1) {
        s  += __shfl_xor_sync(0xffffffffu, s,  o);
        ss += __shfl_xor_sync(0xffffffffu, ss, o);
    }
    __shared__ float shs[4], shss[4];
    if ((tid & 31) == 0) { shs[tid >> 5] = s; shss[tid >> 5] = ss; }
    __syncthreads();
    s  = shs[0]  + shs[1]  + shs[2]  + shs[3];
    ss = shss[0] + shss[1] + shss[2] + shss[3];

    const float mu  = s * (1.0f / ND);
    const float var = ss * (1.0f / ND) - mu * mu;
    const float inv = rsqrtf(var + 1e-5f);

    const float4 g4 = ((const float4*)lng)[tid];
    const float4 b4 = ((const float4*)lnb)[tid];
    float4 o4;
    o4.x = (v.x - mu) * inv * g4.x + b4.x;
    o4.y = (v.y - mu) * inv * g4.y + b4.y;
    o4.z = (v.z - mu) * inv * g4.z + b4.z;
    o4.w = (v.w - mu) * inv * g4.w + b4.w;
    ((float4*)(out + (size_t)row * ND))[tid] = o4;
}

// ---------------------------------------------------------------------------
// Launch
// ---------------------------------------------------------------------------
extern "C" void kernel_launch(void* const* d_in, const int* in_sizes, int n_in,
                              void* d_out, int out_size)
{
    const float* x    = (const float*)d_in[0];   // (B,T,D)
    const float* winp = (const float*)d_in[1];   // (2*DI, D)
    const float* wcf  = (const float*)d_in[2];   // (DI,1,K)
    const float* bcf  = (const float*)d_in[3];   // (DI,)
    const float* wpf  = (const float*)d_in[4];   // (DI,DI)
    const float* bpf  = (const float*)d_in[5];   // (DI,)
    const float* wcb  = (const float*)d_in[6];
    const float* bcb  = (const float*)d_in[7];
    const float* wpb  = (const float*)d_in[8];
    const float* bpb  = (const float*)d_in[9];
    const float* diag = (const float*)d_in[10];  // (DI,)
    const float* gsc  = (const float*)d_in[11];  // (1,)
    const float* wout = (const float*)d_in[12];  // (D, DI)
    const float* lng  = (const float*)d_in[13];  // (D,)
    const float* lnb  = (const float*)d_in[14];  // (D,)
    float* out = (float*)d_out;

    float *pXp, *pZ, *pAf, *pAb, *pGf, *pGb, *pY, *pH;
    cudaGetSymbolAddress((void**)&pXp, g_Xp);
    cudaGetSymbolAddress((void**)&pZ,  g_Z);
    cudaGetSymbolAddress((void**)&pAf, g_Af);
    cudaGetSymbolAddress((void**)&pAb, g_Ab);
    cudaGetSymbolAddress((void**)&pGf, g_Gf);
    cudaGetSymbolAddress((void**)&pGb, g_Gb);
    cudaGetSymbolAddress((void**)&pY,  g_Y);
    cudaGetSymbolAddress((void**)&pH,  g_H);

    const dim3 blk(256);

    // 1) in_proj: xz = x @ Win^T  -> split into Xp, Z
    sgemm128<<<dim3((2 * NDI) / 128, NM / 128), blk>>>(x, winp, pXp, pZ, nullptr, ND, 2 * NDI, 0);

    // 2) depthwise convs -> Af, Ab
    conv_kernel<<<dim3(NDI / 256, NM), 256>>>(wcf, bcf, wcb, bcb);

    // 3) fwd / bwd projections
    sgemm128<<<dim3(NDI / 128, NM / 128), blk>>>(pAf, wpf, pGf, nullptr, nullptr, NDI, NDI, 1);
    sgemm128<<<dim3(NDI / 128, NM / 128), blk>>>(pAb, wpb, pGb, nullptr, nullptr, NDI, NDI, 1);

    // 4) combine + gate -> Y
    combine_kernel<<<(NM * NDI / 4) / 256, 256>>>(bpf, bpb, diag, gsc);

    // 5) out_proj + residual -> H
    sgemm128<<<dim3(ND / 128, NM / 128), blk>>>(pY, wout, pH, nullptr, x, NDI, ND, 2);

    // 6) LayerNorm -> out
    ln_kernel<<<NM, 128>>>(lng, lnb, out);
}

// round 5
// speedup vs baseline: 4.2977x; 4.2977x over previous
#include <cuda_runtime.h>
#include <cuda_bf16.h>

typedef unsigned int u32;

// Problem constants
#define NB   8
#define NT   4096
#define ND   512
#define NDI  1024
#define NM   (NB * NT)   // 32768 rows (B*T)

// ---------------------------------------------------------------------------
// Scratch (static __device__ arrays; no allocations allowed)
// ---------------------------------------------------------------------------
__device__ __nv_bfloat16 g_xbf[NM * ND];        // x in bf16 (GEMM1 A)
__device__ __nv_bfloat16 g_wi [2 * NDI * ND];   // in_proj_w bf16
__device__ __nv_bfloat16 g_wpf[NDI * NDI];      // proj_fwd_w bf16
__device__ __nv_bfloat16 g_wpb[NDI * NDI];      // proj_bwd_w bf16
__device__ __nv_bfloat16 g_wo [ND * NDI];       // out_proj_w bf16
__device__ __nv_bfloat16 g_Xp[NM * NDI];        // x_proj bf16
__device__ __nv_bfloat16 g_Z [NM * NDI];        // z bf16
__device__ __nv_bfloat16 g_Af[NM * NDI];        // conv fwd out bf16
__device__ __nv_bfloat16 g_Ab[NM * NDI];        // conv bwd out bf16
__device__ __nv_bfloat16 g_Sf[NM * NDI];        // silu(proj_fwd + bias) bf16
__device__ __nv_bfloat16 g_Sb[NM * NDI];        // silu(proj_bwd + bias) bf16
__device__ __nv_bfloat16 g_Y [NM * NDI];        // gated mixer output bf16
__device__ float         g_H [NM * ND];         // residual + out_proj (fp32)

__device__ __forceinline__ float silu_f(float x) {
    return x / (1.0f + __expf(-x));
}

__device__ __forceinline__ u32 smem_u32(const void* p) {
    u32 a;
    asm("{ .reg .u64 t; cvta.to.shared.u64 t, %1; cvt.u32.u64 %0, t; }"
        : "=r"(a) : "l"(p));
    return a;
}

// ---------------------------------------------------------------------------
// PTX primitives: cp.async, ldmatrix, mma (all compute_103-base legal)
// ---------------------------------------------------------------------------
__device__ __forceinline__ void cpa16(u32 s, const void* g) {
    asm volatile("cp.async.cg.shared.global [%0], [%1], 16;" :: "r"(s), "l"(g));
}
#define CP_COMMIT()  asm volatile("cp.async.commit_group;" ::: "memory")
#define CP_WAIT(N)   asm volatile("cp.async.wait_group %0;" :: "n"(N) : "memory")

#define LDSM4(r0, r1, r2, r3, addr) \
    asm volatile("ldmatrix.sync.aligned.m8n8.x4.shared.b16 {%0,%1,%2,%3}, [%4];" \
        : "=r"(r0), "=r"(r1), "=r"(r2), "=r"(r3) : "r"(addr))

#define MMA16816(c, a, b) \
    asm volatile("mma.sync.aligned.m16n8k16.row.col.f32.bf16.bf16.f32 " \
        "{%0,%1,%2,%3}, {%4,%5,%6,%7}, {%8,%9}, {%0,%1,%2,%3};" \
        : "+f"((c)[0]), "+f"((c)[1]), "+f"((c)[2]), "+f"((c)[3]) \
        : "r"((a)[0]), "r"((a)[1]), "r"((a)[2]), "r"((a)[3]), \
          "r"((b)[0]), "r"((b)[1]))

// ---------------------------------------------------------------------------
// Warp-MMA GEMM: C[m,n] = sum_k A[m,k]*W[n,k], bf16 in, fp32 accum.
// BM=BN=128, BK=64, 256 threads = 8 warps (2M x 4N), 64x32 warp tiles.
// SW128-swizzled smem, cp.async double buffer, ldmatrix fragments.
// mode 0: split cvt-store: tile n0 <  NDI -> o0 (Xp) [bf16]
//                          tile n0 >= NDI -> o1 (Z)  [bf16]
// mode 1: o0[m,n] = bf16( silu(acc + bias[n]) )
// mode 2: of[m,n] = acc + resid[m,n]   [fp32]
// ---------------------------------------------------------------------------
#define GEMM_SMEM (1024 + 2 * 32768)

__global__ __launch_bounds__(256, 2)
void gemm_mma(const __nv_bfloat16* __restrict__ A, const __nv_bfloat16* __restrict__ W,
              int K, int mode,
              __nv_bfloat16* __restrict__ o0, __nv_bfloat16* __restrict__ o1,
              const float* __restrict__ bias, const float* __restrict__ resid,
              float* __restrict__ of, int Nout)
{
    extern __shared__ char dsm[];
    const u32 dyn  = smem_u32(dsm);
    const u32 base = (dyn + 1023u) & ~1023u;

    const int tid  = threadIdx.x;
    const int wid  = tid >> 5;
    const int lane = tid & 31;
    const int m0   = blockIdx.y << 7;
    const int n0   = blockIdx.x << 7;
    const int warp_m = wid >> 2;      // 0..1
    const int warp_n = wid & 3;       // 0..3

    // buffers: [buf][A(16KB) | B(16KB)]
    const u32 bufA[2] = { base,          base + 32768u };
    const u32 bufB[2] = { base + 16384u, base + 49152u };

    // ---- cp.async assignments: 4 chunks of 16B per thread per tile ----
    int swoff[4];
    const __nv_bfloat16* gA[4];
    const __nv_bfloat16* gB[4];
#pragma unroll
    for (int i = 0; i < 4; ++i) {
        const int idx = i * 256 + tid;
        const int row = idx >> 3;
        const int ch  = idx & 7;
        swoff[i] = row * 128 + ((ch * 16) ^ ((row & 7) << 4));
        gA[i] = A + (size_t)(m0 + row) * K + ch * 8;
        gB[i] = W + (size_t)(n0 + row) * K + ch * 8;
    }

    // ---- ldmatrix per-lane address components ----
    const int blk = lane >> 3;        // 0..3
    const int lr  = lane & 7;
    // A tile: x4 blocks (m0-7/k0-7),(m8-15/k0-7),(m0-7/k8-15),(m8-15/k8-15)
    int aRow[4], aXr[4];
#pragma unroll
    for (int mi = 0; mi < 4; ++mi) {
        const int r = warp_m * 64 + mi * 16 + (blk & 1) * 8 + lr;
        aRow[mi] = r * 128;
        aXr[mi]  = (r & 7) << 4;
    }
    const int koA = (blk >> 1) * 16;
    // B tile (two n8 tiles per x4): blocks (n0-7/k0-7),(n0-7/k8-15),(n8-15/k0-7),(n8-15/k8-15)
    int bRow[2], bXr[2];
#pragma unroll
    for (int np = 0; np < 2; ++np) {
        const int r = warp_n * 32 + np * 16 + (blk >> 1) * 8 + lr;
        bRow[np] = r * 128;
        bXr[np]  = (r & 7) << 4;
    }
    const int koB = (blk & 1) * 16;

    float acc[4][4][4];
#pragma unroll
    for (int mi = 0; mi < 4; ++mi)
#pragma unroll
        for (int ni = 0; ni < 4; ++ni)
#pragma unroll
            for (int j = 0; j < 4; ++j) acc[mi][ni][j] = 0.0f;

    const int S = K >> 6;

    // prologue: load slab 0
#pragma unroll
    for (int i = 0; i < 4; ++i) {
        cpa16(bufA[0] + swoff[i], gA[i]);
        cpa16(bufB[0] + swoff[i], gB[i]);
    }
    CP_COMMIT();

    for (int s = 0; s < S; ++s) {
        if (s + 1 < S) {
            const int nb = (s + 1) & 1;
            const int k0 = (s + 1) << 6;
#pragma unroll
            for (int i = 0; i < 4; ++i) {
                cpa16(bufA[nb] + swoff[i], gA[i] + k0);
                cpa16(bufB[nb] + swoff[i], gB[i] + k0);
            }
            CP_COMMIT();
            CP_WAIT(1);
        } else {
            CP_WAIT(0);
        }
        __syncthreads();

        const u32 sa = bufA[s & 1];
        const u32 sb = bufB[s & 1];
#pragma unroll
        for (int kk = 0; kk < 4; ++kk) {
            u32 a[4][4];
#pragma unroll
            for (int mi = 0; mi < 4; ++mi) {
                const u32 ad = sa + aRow[mi] + ((kk * 32 + koA) ^ aXr[mi]);
                LDSM4(a[mi][0], a[mi][1], a[mi][2], a[mi][3], ad);
            }
            u32 b[4][2];
#pragma unroll
            for (int np = 0; np < 2; ++np) {
                const u32 bd = sb + bRow[np] + ((kk * 32 + koB) ^ bXr[np]);
                LDSM4(b[2*np][0], b[2*np][1], b[2*np+1][0], b[2*np+1][1], bd);
            }
#pragma unroll
            for (int mi = 0; mi < 4; ++mi)
#pragma unroll
                for (int ni = 0; ni < 4; ++ni)
                    MMA16816(acc[mi][ni], a[mi], b[ni]);
        }
        __syncthreads();
    }

    // ---- epilogue ----
    const int mrow0 = m0 + warp_m * 64 + (lane >> 2);
    const int ncol0 = n0 + warp_n * 32 + (lane & 3) * 2;

    if (mode == 2) {
#pragma unroll
        for (int mi = 0; mi < 4; ++mi) {
#pragma unroll
            for (int ni = 0; ni < 4; ++ni) {
                const int m = mrow0 + mi * 16;
                const int n = ncol0 + ni * 8;
                const float* c = acc[mi][ni];
                float2 r0 = *(const float2*)(resid + (size_t)m * Nout + n);
                float2 r1 = *(const float2*)(resid + (size_t)(m + 8) * Nout + n);
                float2 v0 = { c[0] + r0.x, c[1] + r0.y };
                float2 v1 = { c[2] + r1.x, c[3] + r1.y };
                *(float2*)(of + (size_t)m * Nout + n)       = v0;
                *(float2*)(of + (size_t)(m + 8) * Nout + n) = v1;
            }
        }
    } else {
        __nv_bfloat16* dst = o0;
        int nsub = 0;
        if (mode == 0 && n0 >= NDI) { dst = o1; nsub = NDI; }
#pragma unroll
        for (int mi = 0; mi < 4; ++mi) {
#pragma unroll
            for (int ni = 0; ni < 4; ++ni) {
                const int m = mrow0 + mi * 16;
                const int n = ncol0 + ni * 8;
                float c0 = acc[mi][ni][0], c1 = acc[mi][ni][1];
                float c2 = acc[mi][ni][2], c3 = acc[mi][ni][3];
                if (mode == 1) {
                    const float b0 = bias[n], b1 = bias[n + 1];
                    c0 = silu_f(c0 + b0); c1 = silu_f(c1 + b1);
                    c2 = silu_f(c2 + b0); c3 = silu_f(c3 + b1);
                }
                __nv_bfloat162 h0, h1;
                h0.x = __float2bfloat16(c0); h0.y = __float2bfloat16(c1);
                h1.x = __float2bfloat16(c2); h1.y = __float2bfloat16(c3);
                const int nl = n - nsub;
                *(u32*)(dst + (size_t)m * NDI + nl)       = *(u32*)&h0;
                *(u32*)(dst + (size_t)(m + 8) * NDI + nl) = *(u32*)&h1;
            }
        }
    }
}

// ---------------------------------------------------------------------------
// fp32 -> bf16 convert (vectorized by 4)
// ---------------------------------------------------------------------------
__global__ void cvt_kernel(const float* __restrict__ src, __nv_bfloat16* __restrict__ dst, int n4)
{
    int i = blockIdx.x * blockDim.x + threadIdx.x;
    if (i >= n4) return;
    float4 v = ((const float4*)src)[i];
    __nv_bfloat162 h0, h1;
    h0.x = __float2bfloat16(v.x); h0.y = __float2bfloat16(v.y);
    h1.x = __float2bfloat16(v.z); h1.y = __float2bfloat16(v.w);
    uint2 o;
    o.x = *(u32*)&h0; o.y = *(u32*)&h1;
    ((uint2*)dst)[i] = o;
}

// ---------------------------------------------------------------------------
// Depthwise causal (fwd) + anti-causal (bwd) conv, 8 channels per thread.
// ---------------------------------------------------------------------------
__device__ __forceinline__ void unpack8(uint4 v, float* f) {
    __nv_bfloat162 h;
    h = *(__nv_bfloat162*)&v.x; f[0] = __bfloat162float(h.x); f[1] = __bfloat162float(h.y);
    h = *(__nv_bfloat162*)&v.y; f[2] = __bfloat162float(h.x); f[3] = __bfloat162float(h.y);
    h = *(__nv_bfloat162*)&v.z; f[4] = __bfloat162float(h.x); f[5] = __bfloat162float(h.y);
    h = *(__nv_bfloat162*)&v.w; f[6] = __bfloat162float(h.x); f[7] = __bfloat162float(h.y);
}

__device__ __forceinline__ uint4 pack8(const float* f) {
    u32 pk[4];
#pragma unroll
    for (int j = 0; j < 4; ++j) {
        __nv_bfloat162 h;
        h.x = __float2bfloat16(f[2*j]);
        h.y = __float2bfloat16(f[2*j+1]);
        pk[j] = *(u32*)&h;
    }
    return *(uint4*)pk;
}

__global__ void conv_kernel(const float* __restrict__ wf, const float* __restrict__ bf,
                            const float* __restrict__ wb, const float* __restrict__ bb)
{
    const int i = blockIdx.x * blockDim.x + threadIdx.x;   // over NM*NDI/8
    const size_t base = (size_t)i * 8;
    const int c = (int)(base & (NDI - 1));
    const int m = (int)(base >> 10);
    const int t = m & (NT - 1);

    float accf[8], accb[8];
#pragma unroll
    for (int j = 0; j < 8; ++j) { accf[j] = bf[c + j]; accb[j] = bb[c + j]; }

#pragma unroll
    for (int k = 0; k < 7; ++k) {
        if (t - 7 + k >= 0) {
            float xv[8];
            unpack8(*(const uint4*)(g_Xp + (size_t)(m - 7 + k) * NDI + c), xv);
#pragma unroll
            for (int j = 0; j < 8; ++j)
                accf[j] = fmaf(wf[(c + j) * 7 + k], xv[j], accf[j]);
        }
        if (t + 7 - k < NT) {
            float xv[8];
            unpack8(*(const uint4*)(g_Xp + (size_t)(m + 7 - k) * NDI + c), xv);
#pragma unroll
            for (int j = 0; j < 8; ++j)
                accb[j] = fmaf(wb[(c + j) * 7 + k], xv[j], accb[j]);
        }
    }
    *(uint4*)(g_Af + base) = pack8(accf);
    *(uint4*)(g_Ab + base) = pack8(accb);
}

// ---------------------------------------------------------------------------
// Combine: y = fm*Sf + bm*Sb + Xp*diag;  y *= silu(z)*gs   (bf16 in/out)
// ---------------------------------------------------------------------------
__global__ void combine_kernel(const float* __restrict__ diag, const float* __restrict__ gsp)
{
    const int i    = blockIdx.x * blockDim.x + threadIdx.x;
    const size_t base = (size_t)i * 8;
    const int c    = (int)(base & (NDI - 1));
    const int m    = (int)(base >> 10);
    const int t    = m & (NT - 1);

    const float fm = (t > 0)      ? 1.0f : 0.0f;
    const float bm = (t < NT - 1) ? 1.0f : 0.0f;
    const float gs = gsp[0];

    float sf[8], sb[8], xp[8], zz[8];
    unpack8(*(const uint4*)(g_Sf + base), sf);
    unpack8(*(const uint4*)(g_Sb + base), sb);
    unpack8(*(const uint4*)(g_Xp + base), xp);
    unpack8(*(const uint4*)(g_Z  + base), zz);

    const float4 d0 = *(const float4*)(diag + c);
    const float4 d1 = *(const float4*)(diag + c + 4);
    float dg[8] = { d0.x, d0.y, d0.z, d0.w, d1.x, d1.y, d1.z, d1.w };

    float y[8];
#pragma unroll
    for (int j = 0; j < 8; ++j)
        y[j] = (fm * sf[j] + bm * sb[j] + xp[j] * dg[j]) * silu_f(zz[j]) * gs;

    *(uint4*)(g_Y + base) = pack8(y);
}

// ---------------------------------------------------------------------------
// LayerNorm over last dim (512), one block (128 threads) per row.
// ---------------------------------------------------------------------------
__global__ void ln_kernel(const float* __restrict__ lng, const float* __restrict__ lnb,
                          float* __restrict__ out)
{
    const int row = blockIdx.x;
    const int tid = threadIdx.x;                 // 0..127

    const float4 v = ((const float4*)(g_H + (size_t)row * ND))[tid];
    float s  = v.x + v.y + v.z + v.w;
    float ss = v.x*v.x + v.y*v.y + v.z*v.z + v.w*v.w;

#pragma unroll
    for (int o = 16; o > 0; o >>= 1) {
        s  += __shfl_xor_sync(0xffffffffu, s,  o);
        ss += __shfl_xor_sync(0xffffffffu, ss, o);
    }
    __shared__ float shs[4], shss[4];
    if ((tid & 31) == 0) { shs[tid >> 5] = s; shss[tid >> 5] = ss; }
    __syncthreads();
    s  = shs[0]  + shs[1]  + shs[2]  + shs[3];
    ss = shss[0] + shss[1] + shss[2] + shss[3];

    const float mu  = s * (1.0f / ND);
    const float var = ss * (1.0f / ND) - mu * mu;
    const float inv = rsqrtf(var + 1e-5f);

    const float4 g4 = ((const float4*)lng)[tid];
    const float4 b4 = ((const float4*)lnb)[tid];
    float4 o4;
    o4.x = (v.x - mu) * inv * g4.x + b4.x;
    o4.y = (v.y - mu) * inv * g4.y + b4.y;
    o4.z = (v.z - mu) * inv * g4.z + b4.z;
    o4.w = (v.w - mu) * inv * g4.w + b4.w;
    ((float4*)(out + (size_t)row * ND))[tid] = o4;
}

// ---------------------------------------------------------------------------
// Launch
// ---------------------------------------------------------------------------
extern "C" void kernel_launch(void* const* d_in, const int* in_sizes, int n_in,
                              void* d_out, int out_size)
{
    const float* x    = (const float*)d_in[0];   // (B,T,D)
    const float* winp = (const float*)d_in[1];   // (2*DI, D)
    const float* wcf  = (const float*)d_in[2];   // (DI,1,K)
    const float* bcf  = (const float*)d_in[3];   // (DI,)
    const float* wpf  = (const float*)d_in[4];   // (DI,DI)
    const float* bpf  = (const float*)d_in[5];   // (DI,)
    const float* wcb  = (const float*)d_in[6];
    const float* bcb  = (const float*)d_in[7];
    const float* wpb  = (const float*)d_in[8];
    const float* bpb  = (const float*)d_in[9];
    const float* diag = (const float*)d_in[10];  // (DI,)
    const float* gsc  = (const float*)d_in[11];  // (1,)
    const float* wout = (const float*)d_in[12];  // (D, DI)
    const float* lng  = (const float*)d_in[13];  // (D,)
    const float* lnb  = (const float*)d_in[14];  // (D,)
    float* out = (float*)d_out;

    __nv_bfloat16 *pxbf, *pwi, *pwpf, *pwpb, *pwo;
    __nv_bfloat16 *pXp, *pZ, *pAf, *pAb, *pSf, *pSb, *pY;
    float *pH;
    cudaGetSymbolAddress((void**)&pxbf, g_xbf);
    cudaGetSymbolAddress((void**)&pwi,  g_wi);
    cudaGetSymbolAddress((void**)&pwpf, g_wpf);
    cudaGetSymbolAddress((void**)&pwpb, g_wpb);
    cudaGetSymbolAddress((void**)&pwo,  g_wo);
    cudaGetSymbolAddress((void**)&pXp,  g_Xp);
    cudaGetSymbolAddress((void**)&pZ,   g_Z);
    cudaGetSymbolAddress((void**)&pAf,  g_Af);
    cudaGetSymbolAddress((void**)&pAb,  g_Ab);
    cudaGetSymbolAddress((void**)&pSf,  g_Sf);
    cudaGetSymbolAddress((void**)&pSb,  g_Sb);
    cudaGetSymbolAddress((void**)&pY,   g_Y);
    cudaGetSymbolAddress((void**)&pH,   g_H);

    cudaFuncSetAttribute(gemm_mma, cudaFuncAttributeMaxDynamicSharedMemorySize, GEMM_SMEM);

    // 0) fp32 -> bf16 conversions
    cvt_kernel<<<(NM * ND / 4 + 255) / 256, 256>>>(x,    pxbf, NM * ND / 4);
    cvt_kernel<<<(2 * NDI * ND / 4 + 255) / 256, 256>>>(winp, pwi,  2 * NDI * ND / 4);
    cvt_kernel<<<(NDI * NDI / 4 + 255) / 256, 256>>>(wpf,  pwpf, NDI * NDI / 4);
    cvt_kernel<<<(NDI * NDI / 4 + 255) / 256, 256>>>(wpb,  pwpb, NDI * NDI / 4);
    cvt_kernel<<<(ND * NDI / 4 + 255) / 256, 256>>>(wout, pwo,  ND * NDI / 4);

    // 1) in_proj: split into Xp, Z (bf16)
    gemm_mma<<<dim3(2 * NDI / 128, NM / 128), 256, GEMM_SMEM>>>(
        pxbf, pwi, ND, 0, pXp, pZ, nullptr, nullptr, nullptr, 2 * NDI);

    // 2) depthwise convs -> Af, Ab (bf16)
    conv_kernel<<<(NM * NDI / 8) / 256, 256>>>(wcf, bcf, wcb, bcb);

    // 3) fwd / bwd projections with fused bias + silu -> Sf, Sb (bf16)
    gemm_mma<<<dim3(NDI / 128, NM / 128), 256, GEMM_SMEM>>>(
        pAf, pwpf, NDI, 1, pSf, nullptr, bpf, nullptr, nullptr, NDI);
    gemm_mma<<<dim3(NDI / 128, NM / 128), 256, GEMM_SMEM>>>(
        pAb, pwpb, NDI, 1, pSb, nullptr, bpb, nullptr, nullptr, NDI);

    // 4) combine + gate -> Y (bf16)
    combine_kernel<<<(NM * NDI / 8) / 256, 256>>>(diag, gsc);

    // 5) out_proj + residual -> H (fp32)
    gemm_mma<<<dim3(ND / 128, NM / 128), 256, GEMM_SMEM>>>(
        pY, pwo, NDI, 2, nullptr, nullptr, nullptr, x, pH, ND);

    // 6) LayerNorm -> out
    ln_kernel<<<NM, 128>>>(lng, lnb, out);
}

// round 6
// speedup vs baseline: 6.2772x; 1.4606x over previous
#include <cuda_runtime.h>
#include <cuda_bf16.h>

typedef unsigned int u32;

// Problem constants
#define NB   8
#define NT   4096
#define ND   512
#define NDI  1024
#define NM   (NB * NT)   // 32768 rows (B*T)

// ---------------------------------------------------------------------------
// Scratch (static __device__ arrays; no allocations allowed)
// ---------------------------------------------------------------------------
__device__ __nv_bfloat16 g_xbf[NM * ND];        // x in bf16 (GEMM1 A)
__device__ __nv_bfloat16 g_wi [2 * NDI * ND];   // in_proj_w bf16
__device__ __nv_bfloat16 g_wpf[NDI * NDI];      // proj_fwd_w bf16
__device__ __nv_bfloat16 g_wpb[NDI * NDI];      // proj_bwd_w bf16
__device__ __nv_bfloat16 g_wo [ND * NDI];       // out_proj_w bf16
__device__ __nv_bfloat16 g_cwf[7 * NDI];        // conv fwd w, [tap][chan] bf16
__device__ __nv_bfloat16 g_cwb[7 * NDI];        // conv bwd w, [tap][chan] bf16
__device__ __nv_bfloat16 g_Xp[NM * NDI];        // x_proj bf16
__device__ __nv_bfloat16 g_Z [NM * NDI];        // z bf16
__device__ __nv_bfloat16 g_Af[NM * NDI];        // conv fwd out bf16
__device__ __nv_bfloat16 g_Ab[NM * NDI];        // conv bwd out bf16
__device__ __nv_bfloat16 g_Sf[NM * NDI];        // silu(proj_fwd + bias) bf16
__device__ __nv_bfloat16 g_Y [NM * NDI];        // gated mixer output bf16
__device__ float         g_H [NM * ND];         // residual + out_proj (fp32)

__device__ __forceinline__ float silu_f(float x) {
    return x / (1.0f + __expf(-x));
}

__device__ __forceinline__ u32 smem_u32(const void* p) {
    u32 a;
    asm("{ .reg .u64 t; cvta.to.shared.u64 t, %1; cvt.u32.u64 %0, t; }"
        : "=r"(a) : "l"(p));
    return a;
}

// ---------------------------------------------------------------------------
// PTX primitives: cp.async, ldmatrix, mma (all compute_103-base legal)
// ---------------------------------------------------------------------------
__device__ __forceinline__ void cpa16(u32 s, const void* g) {
    asm volatile("cp.async.cg.shared.global [%0], [%1], 16;" :: "r"(s), "l"(g));
}
#define CP_COMMIT()  asm volatile("cp.async.commit_group;" ::: "memory")
#define CP_WAIT(N)   asm volatile("cp.async.wait_group %0;" :: "n"(N) : "memory")

#define LDSM4(r0, r1, r2, r3, addr) \
    asm volatile("ldmatrix.sync.aligned.m8n8.x4.shared.b16 {%0,%1,%2,%3}, [%4];" \
        : "=r"(r0), "=r"(r1), "=r"(r2), "=r"(r3) : "r"(addr))

#define MMA16816(c, a, b) \
    asm volatile("mma.sync.aligned.m16n8k16.row.col.f32.bf16.bf16.f32 " \
        "{%0,%1,%2,%3}, {%4,%5,%6,%7}, {%8,%9}, {%0,%1,%2,%3};" \
        : "+f"((c)[0]), "+f"((c)[1]), "+f"((c)[2]), "+f"((c)[3]) \
        : "r"((a)[0]), "r"((a)[1]), "r"((a)[2]), "r"((a)[3]), \
          "r"((b)[0]), "r"((b)[1]))

// ---------------------------------------------------------------------------
// Warp-MMA GEMM: C[m,n] = sum_k A[m,k]*W[n,k], bf16 in, fp32 accum.
// BM=BN=128, BK=64, 256 threads = 8 warps (2M x 4N), 64x32 warp tiles.
// SW128-swizzled smem, 3-stage cp.async pipeline, one barrier per slab.
// mode 0: split: tile n0 < NDI -> o0 (Xp), else o1 (Z)    [bf16]
// mode 1: o0[m,n] = bf16( silu(acc + bias[n]) )           [bf16]
// mode 2: of[m,n] = acc + resid[m,n]                      [fp32]
// mode 3: sb = silu(acc + bias[n]);  (combine fused)
//         y = (fm*Sf + bm*sb + Xp*diag) * silu(Z) * gs -> o0 (Y) [bf16]
// ---------------------------------------------------------------------------
#define GEMM_SMEM (1024 + 3 * 32768)

__global__ __launch_bounds__(256, 2)
void gemm_mma(const __nv_bfloat16* __restrict__ A, const __nv_bfloat16* __restrict__ W,
              int K, int mode,
              __nv_bfloat16* __restrict__ o0, __nv_bfloat16* __restrict__ o1,
              const float* __restrict__ bias, const float* __restrict__ resid,
              float* __restrict__ of, int Nout,
              const __nv_bfloat16* __restrict__ eSf, const __nv_bfloat16* __restrict__ eXp,
              const __nv_bfloat16* __restrict__ eZ,
              const float* __restrict__ diag, const float* __restrict__ gsp)
{
    extern __shared__ char dsm[];
    const u32 dyn  = smem_u32(dsm);
    const u32 base = (dyn + 1023u) & ~1023u;

    const int tid  = threadIdx.x;
    const int wid  = tid >> 5;
    const int lane = tid & 31;
    const int m0   = blockIdx.y << 7;
    const int n0   = blockIdx.x << 7;
    const int warp_m = wid >> 2;      // 0..1
    const int warp_n = wid & 3;       // 0..3

    // ---- cp.async assignments: 4 chunks of 16B per thread per tile ----
    int swoff[4];
    const __nv_bfloat16* gA[4];
    const __nv_bfloat16* gB[4];
#pragma unroll
    for (int i = 0; i < 4; ++i) {
        const int idx = i * 256 + tid;
        const int row = idx >> 3;
        const int ch  = idx & 7;
        swoff[i] = row * 128 + ((ch * 16) ^ ((row & 7) << 4));
        gA[i] = A + (size_t)(m0 + row) * K + ch * 8;
        gB[i] = W + (size_t)(n0 + row) * K + ch * 8;
    }

    // ---- ldmatrix per-lane address components ----
    const int blk = lane >> 3;        // 0..3
    const int lr  = lane & 7;
    int aRow[4], aXr[4];
#pragma unroll
    for (int mi = 0; mi < 4; ++mi) {
        const int r = warp_m * 64 + mi * 16 + (blk & 1) * 8 + lr;
        aRow[mi] = r * 128;
        aXr[mi]  = (r & 7) << 4;
    }
    const int koA = (blk >> 1) * 16;
    int bRow[2], bXr[2];
#pragma unroll
    for (int np = 0; np < 2; ++np) {
        const int r = warp_n * 32 + np * 16 + (blk >> 1) * 8 + lr;
        bRow[np] = r * 128;
        bXr[np]  = (r & 7) << 4;
    }
    const int koB = (blk & 1) * 16;

    float acc[4][4][4];
#pragma unroll
    for (int mi = 0; mi < 4; ++mi)
#pragma unroll
        for (int ni = 0; ni < 4; ++ni)
#pragma unroll
            for (int j = 0; j < 4; ++j) acc[mi][ni][j] = 0.0f;

    const int S = K >> 6;

    // ---- prologue: issue slabs 0 and 1 (two commit groups) ----
#pragma unroll
    for (int i = 0; i < 4; ++i) {
        cpa16(base + swoff[i], gA[i]);
        cpa16(base + 16384u + swoff[i], gB[i]);
    }
    CP_COMMIT();
    if (S > 1) {
#pragma unroll
        for (int i = 0; i < 4; ++i) {
            cpa16(base + 32768u + swoff[i], gA[i] + 64);
            cpa16(base + 49152u + swoff[i], gB[i] + 64);
        }
    }
    CP_COMMIT();

    // rotating stage pointers (kept in registers)
    u32 ar = base;                 // read stage A
    u32 aw = base + 2u * 32768u;   // write stage A (stage 2 first)
    const u32 top = base + 3u * 32768u;

    for (int s = 0; s < S; ++s) {
        if (s < S - 1) { CP_WAIT(1); } else { CP_WAIT(0); }
        __syncthreads();

        if (s + 2 < S) {
            const int k0 = (s + 2) << 6;
#pragma unroll
            for (int i = 0; i < 4; ++i) {
                cpa16(aw + swoff[i], gA[i] + k0);
                cpa16(aw + 16384u + swoff[i], gB[i] + k0);
            }
            aw += 32768u; if (aw == top) aw = base;
        }
        CP_COMMIT();

        const u32 sa = ar;
        const u32 sb = ar + 16384u;
#pragma unroll
        for (int kk = 0; kk < 4; ++kk) {
            u32 a[4][4];
#pragma unroll
            for (int mi = 0; mi < 4; ++mi) {
                const u32 ad = sa + aRow[mi] + ((kk * 32 + koA) ^ aXr[mi]);
                LDSM4(a[mi][0], a[mi][1], a[mi][2], a[mi][3], ad);
            }
            u32 b[4][2];
#pragma unroll
            for (int np = 0; np < 2; ++np) {
                const u32 bd = sb + bRow[np] + ((kk * 32 + koB) ^ bXr[np]);
                LDSM4(b[2*np][0], b[2*np][1], b[2*np+1][0], b[2*np+1][1], bd);
            }
#pragma unroll
            for (int mi = 0; mi < 4; ++mi)
#pragma unroll
                for (int ni = 0; ni < 4; ++ni)
                    MMA16816(acc[mi][ni], a[mi], b[ni]);
        }
        ar += 32768u; if (ar == top) ar = base;
    }

    // ---- epilogue ----
    const int mrow0 = m0 + warp_m * 64 + (lane >> 2);
    const int ncol0 = n0 + warp_n * 32 + (lane & 3) * 2;

    if (mode == 2) {
#pragma unroll
        for (int mi = 0; mi < 4; ++mi) {
#pragma unroll
            for (int ni = 0; ni < 4; ++ni) {
                const int m = mrow0 + mi * 16;
                const int n = ncol0 + ni * 8;
                const float* c = acc[mi][ni];
                float2 r0 = *(const float2*)(resid + (size_t)m * Nout + n);
                float2 r1 = *(const float2*)(resid + (size_t)(m + 8) * Nout + n);
                float2 v0 = { c[0] + r0.x, c[1] + r0.y };
                float2 v1 = { c[2] + r1.x, c[3] + r1.y };
                *(float2*)(of + (size_t)m * Nout + n)       = v0;
                *(float2*)(of + (size_t)(m + 8) * Nout + n) = v1;
            }
        }
    } else if (mode == 3) {
        const float gs = gsp[0];
#pragma unroll
        for (int mi = 0; mi < 4; ++mi) {
            const int m  = mrow0 + mi * 16;
            const int t0 = m & (NT - 1);
            const int t1 = (m + 8) & (NT - 1);
            const float fm0 = (t0 > 0) ? 1.0f : 0.0f;
            const float bm0 = (t0 < NT - 1) ? 1.0f : 0.0f;
            const float fm1 = (t1 > 0) ? 1.0f : 0.0f;
            const float bm1 = (t1 < NT - 1) ? 1.0f : 0.0f;
#pragma unroll
            for (int ni = 0; ni < 4; ++ni) {
                const int n = ncol0 + ni * 8;
                const size_t o0i = (size_t)m * NDI + n;
                const size_t o1i = (size_t)(m + 8) * NDI + n;
                const float2 dg = *(const float2*)(diag + n);
                const float b0 = bias[n], b1 = bias[n + 1];

                __nv_bfloat162 sf0 = *(const __nv_bfloat162*)(eSf + o0i);
                __nv_bfloat162 sf1 = *(const __nv_bfloat162*)(eSf + o1i);
                __nv_bfloat162 xp0 = *(const __nv_bfloat162*)(eXp + o0i);
                __nv_bfloat162 xp1 = *(const __nv_bfloat162*)(eXp + o1i);
                __nv_bfloat162 z0  = *(const __nv_bfloat162*)(eZ  + o0i);
                __nv_bfloat162 z1  = *(const __nv_bfloat162*)(eZ  + o1i);

                const float sb00 = silu_f(acc[mi][ni][0] + b0);
                const float sb01 = silu_f(acc[mi][ni][1] + b1);
                const float sb10 = silu_f(acc[mi][ni][2] + b0);
                const float sb11 = silu_f(acc[mi][ni][3] + b1);

                float y00 = (fm0 * __bfloat162float(sf0.x) + bm0 * sb00 +
                             __bfloat162float(xp0.x) * dg.x) * silu_f(__bfloat162float(z0.x)) * gs;
                float y01 = (fm0 * __bfloat162float(sf0.y) + bm0 * sb01 +
                             __bfloat162float(xp0.y) * dg.y) * silu_f(__bfloat162float(z0.y)) * gs;
                float y10 = (fm1 * __bfloat162float(sf1.x) + bm1 * sb10 +
                             __bfloat162float(xp1.x) * dg.x) * silu_f(__bfloat162float(z1.x)) * gs;
                float y11 = (fm1 * __bfloat162float(sf1.y) + bm1 * sb11 +
                             __bfloat162float(xp1.y) * dg.y) * silu_f(__bfloat162float(z1.y)) * gs;

                __nv_bfloat162 h0, h1;
                h0.x = __float2bfloat16(y00); h0.y = __float2bfloat16(y01);
                h1.x = __float2bfloat16(y10); h1.y = __float2bfloat16(y11);
                *(u32*)(o0 + o0i) = *(u32*)&h0;
                *(u32*)(o0 + o1i) = *(u32*)&h1;
            }
        }
    } else {
        __nv_bfloat16* dst = o0;
        int nsub = 0;
        if (mode == 0 && n0 >= NDI) { dst = o1; nsub = NDI; }
#pragma unroll
        for (int mi = 0; mi < 4; ++mi) {
#pragma unroll
            for (int ni = 0; ni < 4; ++ni) {
                const int m = mrow0 + mi * 16;
                const int n = ncol0 + ni * 8;
                float c0 = acc[mi][ni][0], c1 = acc[mi][ni][1];
                float c2 = acc[mi][ni][2], c3 = acc[mi][ni][3];
                if (mode == 1) {
                    const float b0 = bias[n], b1 = bias[n + 1];
                    c0 = silu_f(c0 + b0); c1 = silu_f(c1 + b1);
                    c2 = silu_f(c2 + b0); c3 = silu_f(c3 + b1);
                }
                __nv_bfloat162 h0, h1;
                h0.x = __float2bfloat16(c0); h0.y = __float2bfloat16(c1);
                h1.x = __float2bfloat16(c2); h1.y = __float2bfloat16(c3);
                const int nl = n - nsub;
                *(u32*)(dst + (size_t)m * NDI + nl)       = *(u32*)&h0;
                *(u32*)(dst + (size_t)(m + 8) * NDI + nl) = *(u32*)&h1;
            }
        }
    }
}

// ---------------------------------------------------------------------------
// fp32 -> bf16 convert (vectorized by 4)
// ---------------------------------------------------------------------------
__global__ void cvt_kernel(const float* __restrict__ src, __nv_bfloat16* __restrict__ dst, int n4)
{
    int i = blockIdx.x * blockDim.x + threadIdx.x;
    if (i >= n4) return;
    float4 v = ((const float4*)src)[i];
    __nv_bfloat162 h0, h1;
    h0.x = __float2bfloat16(v.x); h0.y = __float2bfloat16(v.y);
    h1.x = __float2bfloat16(v.z); h1.y = __float2bfloat16(v.w);
    uint2 o;
    o.x = *(u32*)&h0; o.y = *(u32*)&h1;
    ((uint2*)dst)[i] = o;
}

// Conv weight transpose: [c][7] fp32 -> [tap][c] bf16
__global__ void convw_prep(const float* __restrict__ wf, const float* __restrict__ wb)
{
    int i = blockIdx.x * blockDim.x + threadIdx.x;
    if (i >= 7 * NDI) return;
    const int j = i / NDI, c = i - j * NDI;
    g_cwf[i] = __float2bfloat16(wf[c * 7 + j]);
    g_cwb[i] = __float2bfloat16(wb[c * 7 + j]);
}

// ---------------------------------------------------------------------------
// Depthwise causal (fwd) + anti-causal (bwd) conv, smem-tiled.
// Tile: 128 t-rows x 64 channels; strip of 142 rows loaded once.
// ---------------------------------------------------------------------------
#define CT_M 128
#define CT_C 64

__device__ __forceinline__ void unpack8s(uint4 v, float* f) {
    __nv_bfloat162 h;
    h = *(__nv_bfloat162*)&v.x; f[0] = __bfloat162float(h.x); f[1] = __bfloat162float(h.y);
    h = *(__nv_bfloat162*)&v.y; f[2] = __bfloat162float(h.x); f[3] = __bfloat162float(h.y);
    h = *(__nv_bfloat162*)&v.z; f[4] = __bfloat162float(h.x); f[5] = __bfloat162float(h.y);
    h = *(__nv_bfloat162*)&v.w; f[6] = __bfloat162float(h.x); f[7] = __bfloat162float(h.y);
}

__device__ __forceinline__ uint4 pack8s(const float* f) {
    u32 pk[4];
#pragma unroll
    for (int j = 0; j < 4; ++j) {
        __nv_bfloat162 h;
        h.x = __float2bfloat16(f[2*j]);
        h.y = __float2bfloat16(f[2*j+1]);
        pk[j] = *(u32*)&h;
    }
    return *(uint4*)pk;
}

__global__ __launch_bounds__(256)
void conv_kernel(const float* __restrict__ bfc, const float* __restrict__ bbc)
{
    __shared__ __nv_bfloat16 sx[142][CT_C];
    __shared__ float swf[7][CT_C], swb[7][CT_C];
    __shared__ float sbf[CT_C], sbb[CT_C];

    const int c0  = blockIdx.x * CT_C;
    const int m0  = blockIdx.y * CT_M;
    const int lo  = m0 & ~(NT - 1);        // batch start row
    const int hi  = lo + NT;
    const int tid = threadIdx.x;

    // weights -> smem (fp32)
    if (tid < 7 * CT_C / 8) {              // 56 threads, 8 ch each
        const int j = tid >> 3, cc = (tid & 7) * 8;
        float f[8];
        uint4 vf = *(const uint4*)(g_cwf + j * NDI + c0 + cc);
        unpack8s(vf, f);
#pragma unroll
        for (int q = 0; q < 8; ++q) swf[j][cc + q] = f[q];
        uint4 vb = *(const uint4*)(g_cwb + j * NDI + c0 + cc);
        unpack8s(vb, f);
#pragma unroll
        for (int q = 0; q < 8; ++q) swb[j][cc + q] = f[q];
    }
    if (tid >= 64 && tid < 64 + CT_C / 4) {
        const int q = (tid - 64) * 4;
        *(float4*)&sbf[q] = *(const float4*)(bfc + c0 + q);
        *(float4*)&sbb[q] = *(const float4*)(bbc + c0 + q);
    }

    // Xp strip: rows m0-7 .. m0+134, zero outside batch
    for (int u = tid; u < 142 * 8; u += 256) {
        const int r = u >> 3, cc = (u & 7) * 8;
        const int m = m0 - 7 + r;
        uint4 v = make_uint4(0, 0, 0, 0);
        if (m >= lo && m < hi)
            v = *(const uint4*)(g_Xp + (size_t)m * NDI + c0 + cc);
        *(uint4*)&sx[r][cc] = v;
    }
    __syncthreads();

    // compute: 128 rows x 8 uint4 units
    for (int u = tid; u < CT_M * 8; u += 256) {
        const int r  = u >> 3, cc = (u & 7) * 8;
        const int m  = m0 + r;
        float accf[8], accb[8];
#pragma unroll
        for (int q = 0; q < 8; ++q) { accf[q] = sbf[cc + q]; accb[q] = sbb[cc + q]; }
#pragma unroll
        for (int k = 0; k < 7; ++k) {
            float xf[8], xb[8];
            unpack8s(*(const uint4*)&sx[r + k][cc], xf);          // Xp[m-7+k]
            unpack8s(*(const uint4*)&sx[r + 14 - k][cc], xb);     // Xp[m+7-k]
#pragma unroll
            for (int q = 0; q < 8; ++q) {
                accf[q] = fmaf(swf[k][cc + q], xf[q], accf[q]);
                accb[q] = fmaf(swb[k][cc + q], xb[q], accb[q]);
            }
        }
        const size_t o = (size_t)m * NDI + c0 + cc;
        *(uint4*)(g_Af + o) = pack8s(accf);
        *(uint4*)(g_Ab + o) = pack8s(accb);
    }
}

// ---------------------------------------------------------------------------
// LayerNorm over last dim (512), one block (128 threads) per row.
// ---------------------------------------------------------------------------
__global__ void ln_kernel(const float* __restrict__ lng, const float* __restrict__ lnb,
                          float* __restrict__ out)
{
    const int row = blockIdx.x;
    const int tid = threadIdx.x;                 // 0..127

    const float4 v = ((const float4*)(g_H + (size_t)row * ND))[tid];
    float s  = v.x + v.y + v.z + v.w;
    float ss = v.x*v.x + v.y*v.y + v.z*v.z + v.w*v.w;

#pragma unroll
    for (int o = 16; o > 0; o >>= 1) {
        s  += __shfl_xor_sync(0xffffffffu, s,  o);
        ss += __shfl_xor_sync(0xffffffffu, ss, o);
    }
    __shared__ float shs[4], shss[4];
    if ((tid & 31) == 0) { shs[tid >> 5] = s; shss[tid >> 5] = ss; }
    __syncthreads();
    s  = shs[0]  + shs[1]  + shs[2]  + shs[3];
    ss = shss[0] + shss[1] + shss[2] + shss[3];

    const float mu  = s * (1.0f / ND);
    const float var = ss * (1.0f / ND) - mu * mu;
    const float inv = rsqrtf(var + 1e-5f);

    const float4 g4 = ((const float4*)lng)[tid];
    const float4 b4 = ((const float4*)lnb)[tid];
    float4 o4;
    o4.x = (v.x - mu) * inv * g4.x + b4.x;
    o4.y = (v.y - mu) * inv * g4.y + b4.y;
    o4.z = (v.z - mu) * inv * g4.z + b4.z;
    o4.w = (v.w - mu) * inv * g4.w + b4.w;
    ((float4*)(out + (size_t)row * ND))[tid] = o4;
}

// ---------------------------------------------------------------------------
// Launch
// ---------------------------------------------------------------------------
extern "C" void kernel_launch(void* const* d_in, const int* in_sizes, int n_in,
                              void* d_out, int out_size)
{
    const float* x    = (const float*)d_in[0];   // (B,T,D)
    const float* winp = (const float*)d_in[1];   // (2*DI, D)
    const float* wcf  = (const float*)d_in[2];   // (DI,1,K)
    const float* bcf  = (const float*)d_in[3];   // (DI,)
    const float* wpf  = (const float*)d_in[4];   // (DI,DI)
    const float* bpf  = (const float*)d_in[5];   // (DI,)
    const float* wcb  = (const float*)d_in[6];
    const float* bcb  = (const float*)d_in[7];
    const float* wpb  = (const float*)d_in[8];
    const float* bpb  = (const float*)d_in[9];
    const float* diag = (const float*)d_in[10];  // (DI,)
    const float* gsc  = (const float*)d_in[11];  // (1,)
    const float* wout = (const float*)d_in[12];  // (D, DI)
    const float* lng  = (const float*)d_in[13];  // (D,)
    const float* lnb  = (const float*)d_in[14];  // (D,)
    float* out = (float*)d_out;

    __nv_bfloat16 *pxbf, *pwi, *pwpf, *pwpb, *pwo;
    __nv_bfloat16 *pXp, *pZ, *pAf, *pAb, *pSf, *pY;
    float *pH;
    cudaGetSymbolAddress((void**)&pxbf, g_xbf);
    cudaGetSymbolAddress((void**)&pwi,  g_wi);
    cudaGetSymbolAddress((void**)&pwpf, g_wpf);
    cudaGetSymbolAddress((void**)&pwpb, g_wpb);
    cudaGetSymbolAddress((void**)&pwo,  g_wo);
    cudaGetSymbolAddress((void**)&pXp,  g_Xp);
    cudaGetSymbolAddress((void**)&pZ,   g_Z);
    cudaGetSymbolAddress((void**)&pAf,  g_Af);
    cudaGetSymbolAddress((void**)&pAb,  g_Ab);
    cudaGetSymbolAddress((void**)&pSf,  g_Sf);
    cudaGetSymbolAddress((void**)&pY,   g_Y);
    cudaGetSymbolAddress((void**)&pH,   g_H);

    cudaFuncSetAttribute(gemm_mma, cudaFuncAttributeMaxDynamicSharedMemorySize, GEMM_SMEM);

    // 0) fp32 -> bf16 conversions + conv weight transpose
    cvt_kernel<<<(NM * ND / 4 + 255) / 256, 256>>>(x,    pxbf, NM * ND / 4);
    cvt_kernel<<<(2 * NDI * ND / 4 + 255) / 256, 256>>>(winp, pwi,  2 * NDI * ND / 4);
    cvt_kernel<<<(NDI * NDI / 4 + 255) / 256, 256>>>(wpf,  pwpf, NDI * NDI / 4);
    cvt_kernel<<<(NDI * NDI / 4 + 255) / 256, 256>>>(wpb,  pwpb, NDI * NDI / 4);
    cvt_kernel<<<(ND * NDI / 4 + 255) / 256, 256>>>(wout, pwo,  ND * NDI / 4);
    convw_prep<<<(7 * NDI + 255) / 256, 256>>>(wcf, wcb);

    // 1) in_proj: split into Xp, Z (bf16)
    gemm_mma<<<dim3(2 * NDI / 128, NM / 128), 256, GEMM_SMEM>>>(
        pxbf, pwi, ND, 0, pXp, pZ, nullptr, nullptr, nullptr, 2 * NDI,
        nullptr, nullptr, nullptr, nullptr, nullptr);

    // 2) depthwise convs -> Af, Ab (bf16)
    conv_kernel<<<dim3(NDI / CT_C, NM / CT_M), 256>>>(bcf, bcb);

    // 3) fwd proj with fused bias + silu -> Sf (bf16)
    gemm_mma<<<dim3(NDI / 128, NM / 128), 256, GEMM_SMEM>>>(
        pAf, pwpf, NDI, 1, pSf, nullptr, bpf, nullptr, nullptr, NDI,
        nullptr, nullptr, nullptr, nullptr, nullptr);

    // 4) bwd proj with fused bias + silu + combine + gate -> Y (bf16)
    gemm_mma<<<dim3(NDI / 128, NM / 128), 256, GEMM_SMEM>>>(
        pAb, pwpb, NDI, 3, pY, nullptr, bpb, nullptr, nullptr, NDI,
        pSf, pXp, pZ, diag, gsc);

    // 5) out_proj + residual -> H (fp32)
    gemm_mma<<<dim3(ND / 128, NM / 128), 256, GEMM_SMEM>>>(
        pY, pwo, NDI, 2, nullptr, nullptr, nullptr, x, pH, ND,
        nullptr, nullptr, nullptr, nullptr, nullptr);

    // 6) LayerNorm -> out
    ln_kernel<<<NM, 128>>>(lng, lnb, out);
}